// round 5
// baseline (speedup 1.0000x reference)
#include <cuda_runtime.h>

// WeightedLoss: mean over 64M elems of (target==1 ? 1-sigmoid(pred) : 0.1)
// 1 - sigmoid(x) = 0.5*(1 - tanh(x/2))  -> single MUFU.TANH per element
//
// Single fused kernel, 512 MiB HBM stream, grid = fully-resident 1184 blocks.
// Explicit 4x unroll: 8 independent LDG.E.128 batched per iteration (MLP_eff~8).
// Last-block-done final reduce (deterministic, fixed order).

#define NBLOCKS (148 * 8)
#define NTHREADS 256

__device__ float g_partials[NBLOCKS];
__device__ unsigned int g_arrive = 0;   // re-armed to 0 by the last block each run

__device__ __forceinline__ float elem_loss(float p, int t) {
    // 1 - sigmoid(p) = 0.5 - 0.5*tanh(p/2); MUFU.TANH
    float s = 0.5f - 0.5f * __tanhf(0.5f * p);
    return (t == 1) ? s : 0.1f;
}

__global__ __launch_bounds__(NTHREADS)
void wl_fused_kernel(const float* __restrict__ pred,
                     const int* __restrict__ tgt,
                     int n, float inv_n,
                     float* __restrict__ out)
{
    const float4* __restrict__ p4 = reinterpret_cast<const float4*>(pred);
    const int4*   __restrict__ t4 = reinterpret_cast<const int4*>(tgt);
    const int n4 = n >> 2;

    const int stride = gridDim.x * blockDim.x;
    int i = blockIdx.x * blockDim.x + threadIdx.x;

    float acc = 0.0f;

    // 4x unrolled: batch 8 independent 128-bit loads before any compute
    for (; i + 3 * stride < n4; i += 4 * stride) {
        float4 p0 = p4[i];
        float4 p1 = p4[i + stride];
        float4 p2 = p4[i + 2 * stride];
        float4 p3 = p4[i + 3 * stride];
        int4   t0 = t4[i];
        int4   t1 = t4[i + stride];
        int4   t2 = t4[i + 2 * stride];
        int4   t3 = t4[i + 3 * stride];

        acc += elem_loss(p0.x, t0.x) + elem_loss(p0.y, t0.y)
             + elem_loss(p0.z, t0.z) + elem_loss(p0.w, t0.w);
        acc += elem_loss(p1.x, t1.x) + elem_loss(p1.y, t1.y)
             + elem_loss(p1.z, t1.z) + elem_loss(p1.w, t1.w);
        acc += elem_loss(p2.x, t2.x) + elem_loss(p2.y, t2.y)
             + elem_loss(p2.z, t2.z) + elem_loss(p2.w, t2.w);
        acc += elem_loss(p3.x, t3.x) + elem_loss(p3.y, t3.y)
             + elem_loss(p3.z, t3.z) + elem_loss(p3.w, t3.w);
    }
    // remainder
    for (; i < n4; i += stride) {
        float4 p = p4[i];
        int4   t = t4[i];
        acc += elem_loss(p.x, t.x) + elem_loss(p.y, t.y)
             + elem_loss(p.z, t.z) + elem_loss(p.w, t.w);
    }

    // intra-block reduce
    #pragma unroll
    for (int o = 16; o > 0; o >>= 1)
        acc += __shfl_xor_sync(0xffffffffu, acc, o);

    __shared__ float sw[NTHREADS / 32];
    __shared__ bool s_last;
    if ((threadIdx.x & 31) == 0) sw[threadIdx.x >> 5] = acc;
    __syncthreads();

    if (threadIdx.x < 32) {
        float v = (threadIdx.x < NTHREADS / 32) ? sw[threadIdx.x] : 0.0f;
        #pragma unroll
        for (int o = 4; o > 0; o >>= 1)
            v += __shfl_xor_sync(0xffffffffu, v, o);
        if (threadIdx.x == 0) {
            g_partials[blockIdx.x] = v;
            __threadfence();
            unsigned int prev = atomicAdd(&g_arrive, 1u);
            s_last = (prev == (unsigned int)(gridDim.x - 1));
        }
    }
    __syncthreads();

    // last block performs the final reduction (fixed order: deterministic)
    if (s_last) {
        float a = 0.0f;
        for (int j = threadIdx.x; j < NBLOCKS; j += NTHREADS)
            a += g_partials[j];

        #pragma unroll
        for (int o = 16; o > 0; o >>= 1)
            a += __shfl_xor_sync(0xffffffffu, a, o);

        __shared__ float sw2[NTHREADS / 32];
        if ((threadIdx.x & 31) == 0) sw2[threadIdx.x >> 5] = a;
        __syncthreads();

        if (threadIdx.x < 32) {
            float v = (threadIdx.x < NTHREADS / 32) ? sw2[threadIdx.x] : 0.0f;
            #pragma unroll
            for (int o = 4; o > 0; o >>= 1)
                v += __shfl_xor_sync(0xffffffffu, v, o);
            if (threadIdx.x == 0) {
                out[0] = v * inv_n;
                __threadfence();
                g_arrive = 0;   // re-arm for next graph replay
            }
        }
    }
}

extern "C" void kernel_launch(void* const* d_in, const int* in_sizes, int n_in,
                              void* d_out, int out_size)
{
    const float* pred = (const float*)d_in[0];
    const int*   tgt  = (const int*)d_in[1];
    float*       out  = (float*)d_out;
    const int n = in_sizes[0];

    wl_fused_kernel<<<NBLOCKS, NTHREADS>>>(pred, tgt, n, 1.0f / (float)n, out);
}